// round 4
// baseline (speedup 1.0000x reference)
#include <cuda_runtime.h>
#include <cuda_bf16.h>
#include <math.h>

// Problem constants (fixed by the dataset)
#define MAXN 100000
#define MAXE 1600000
#define F 32            // F_IN == F_OUT == 32

// Scratch (static device globals; no allocation allowed)
__device__ int   d_idx64;            // 1 if edge_index is int64, 0 if int32
__device__ float d_deg[MAXN];        // degree, then overwritten with dinv
__device__ float d_norm[MAXE];       // per-edge normalized Laplacian coefficient
__device__ float d_tx1[MAXN * F];    // L_hat @ x

// ---------------------------------------------------------------------------
// Edge-index access helper: dtype decided at runtime by k_detect.
// ---------------------------------------------------------------------------
__device__ __forceinline__ void load_edge(const void* __restrict__ ei, int E,
                                          int e, int& s, int& d) {
    if (d_idx64) {
        const long long* p = (const long long*)ei;
        s = (int)p[e];
        d = (int)p[E + e];
    } else {
        const int* p = (const int*)ei;
        s = p[e];
        d = p[E + e];
    }
}

// ---------------------------------------------------------------------------
// K-1: detect edge_index dtype. Under int64 interpretation of int32 data,
// values become v0 | (v1<<32) which is >= 2^32 whenever v1 != 0 (prob 1-1e-5
// per sample). 64 samples from both halves -> essentially certain detection.
// ---------------------------------------------------------------------------
__global__ void k_detect(const void* __restrict__ ei, int E, int n) {
    const long long* p = (const long long*)ei;
    int ok = 1;
    for (int i = 0; i < 32; i++) {
        long long a = p[i];
        long long b = p[E + i];
        if (a < 0 || a >= n || b < 0 || b >= n) { ok = 0; break; }
    }
    d_idx64 = ok;
}

// ---------------------------------------------------------------------------
// K0: zero deg and tx1
// ---------------------------------------------------------------------------
__global__ void k_zero(int n) {
    int i = blockIdx.x * blockDim.x + threadIdx.x;
    int tot = n * F;
    if (i < tot) d_tx1[i] = 0.0f;
    if (i < n)   d_deg[i] = 0.0f;
}

// ---------------------------------------------------------------------------
// K1: deg[src] += w   (self-loop weights zeroed)
// ---------------------------------------------------------------------------
__global__ void k_degree(const void* __restrict__ ei,
                         const float* __restrict__ ew, int E, int n) {
    int e = blockIdx.x * blockDim.x + threadIdx.x;
    if (e >= E) return;
    int s, d;
    load_edge(ei, E, e, s, d);
    if ((unsigned)s >= (unsigned)n || (unsigned)d >= (unsigned)n) return;
    float w = (s == d) ? 0.0f : ew[e];
    if (w != 0.0f) atomicAdd(&d_deg[s], w);
}

// ---------------------------------------------------------------------------
// K2: deg -> dinv = deg>0 ? rsqrt(deg) : 0
// ---------------------------------------------------------------------------
__global__ void k_dinv(int n) {
    int i = blockIdx.x * blockDim.x + threadIdx.x;
    if (i >= n) return;
    float v = d_deg[i];
    d_deg[i] = (v > 0.0f) ? rsqrtf(v) : 0.0f;
}

// ---------------------------------------------------------------------------
// K3: per-edge coefficient  norm = -dinv[src] * w * dinv[dst]
// ---------------------------------------------------------------------------
__global__ void k_norm(const void* __restrict__ ei,
                       const float* __restrict__ ew, int E, int n) {
    int e = blockIdx.x * blockDim.x + threadIdx.x;
    if (e >= E) return;
    int s, d;
    load_edge(ei, E, e, s, d);
    if ((unsigned)s >= (unsigned)n || (unsigned)d >= (unsigned)n) {
        d_norm[e] = 0.0f;
        return;
    }
    float w = (s == d) ? 0.0f : ew[e];
    d_norm[e] = -d_deg[s] * w * d_deg[d];
}

// ---------------------------------------------------------------------------
// K4: scatter  tx1[dst] += norm * x[src]   (vectorized reduced atomics)
// One thread per (edge, quad-of-4-features): 8 threads per edge.
// Consecutive threads share the same edge -> index loads coalesce/broadcast.
// ---------------------------------------------------------------------------
__global__ void k_scatter(const float* __restrict__ x,
                          const void* __restrict__ ei, int E, int n) {
    int t = blockIdx.x * blockDim.x + threadIdx.x;
    int e = t >> 3;
    int q = t & 7;
    if (e >= E) return;
    float c = d_norm[e];
    if (c == 0.0f) return;
    int s, d;
    load_edge(ei, E, e, s, d);
    if ((unsigned)s >= (unsigned)n || (unsigned)d >= (unsigned)n) return;
    const float4* x4 = reinterpret_cast<const float4*>(x);
    float4 xv = x4[s * (F / 4) + q];
    float* dst = &d_tx1[d * F + q * 4];
    asm volatile("red.global.add.v4.f32 [%0], {%1, %2, %3, %4};"
                 :: "l"(dst), "f"(c * xv.x), "f"(c * xv.y),
                    "f"(c * xv.z), "f"(c * xv.w)
                 : "memory");
}

// ---------------------------------------------------------------------------
// K5: gates + output.  Since H_prev = C_prev = 0:
//   I = sigmoid(x@Wx[0,0] + tx1@Wx[0,1] + bx[0] + bh[0] + b_gate[0])
//   T = tanh   (x@Wx[2,0] + tx1@Wx[2,1] + bx[2] + bh[2] + b_gate[2])
//   C = I*T
//   O = sigmoid(x@Wx[3,0] + tx1@Wx[3,1] + bx[3] + bh[3] + b_gate[3] + wc[2]*C)
//   H = O*tanh(C);  out = relu(H)@lin_w + lin_b
// One warp per node, lane = output feature.
// ---------------------------------------------------------------------------
__global__ void k_gates(const float* __restrict__ x,
                        const float* __restrict__ Wx,
                        const float* __restrict__ bx,
                        const float* __restrict__ bh,
                        const float* __restrict__ wc,
                        const float* __restrict__ bgate,
                        const float* __restrict__ linw,
                        const float* __restrict__ linb,
                        float* __restrict__ out, int n) {
    __shared__ float sWi0[F * F], sWi1[F * F];
    __shared__ float sWc0[F * F], sWc1[F * F];
    __shared__ float sWo0[F * F], sWo1[F * F];
    __shared__ float sBi[F], sBc[F], sBo[F], sWc2[F], sLw[F];
    __shared__ float sLb;

    int tid = threadIdx.x;
    // Wx layout: [4][2][32][32]; matrix (g,k) starts at (g*2+k)*F*F
    for (int i = tid; i < F * F; i += blockDim.x) {
        sWi0[i] = Wx[(0 * 2 + 0) * F * F + i];
        sWi1[i] = Wx[(0 * 2 + 1) * F * F + i];
        sWc0[i] = Wx[(2 * 2 + 0) * F * F + i];
        sWc1[i] = Wx[(2 * 2 + 1) * F * F + i];
        sWo0[i] = Wx[(3 * 2 + 0) * F * F + i];
        sWo1[i] = Wx[(3 * 2 + 1) * F * F + i];
    }
    if (tid < F) {
        sBi[tid]  = bx[0 * F + tid] + bh[0 * F + tid] + bgate[0 * F + tid];
        sBc[tid]  = bx[2 * F + tid] + bh[2 * F + tid] + bgate[2 * F + tid];
        sBo[tid]  = bx[3 * F + tid] + bh[3 * F + tid] + bgate[3 * F + tid];
        sWc2[tid] = wc[2 * F + tid];
        sLw[tid]  = linw[tid];
        if (tid == 0) sLb = linb[0];
    }
    __syncthreads();

    int warp = tid >> 5;
    int lane = tid & 31;
    int node = blockIdx.x * (blockDim.x >> 5) + warp;
    if (node >= n) return;

    float xr = x[node * F + lane];
    float tr = d_tx1[node * F + lane];

    float ai = sBi[lane];
    float ac = sBc[lane];
    float ao = sBo[lane];

#pragma unroll
    for (int f = 0; f < F; f++) {
        float xf = __shfl_sync(0xffffffffu, xr, f);
        float tf = __shfl_sync(0xffffffffu, tr, f);
        ai += xf * sWi0[f * F + lane] + tf * sWi1[f * F + lane];
        ac += xf * sWc0[f * F + lane] + tf * sWc1[f * F + lane];
        ao += xf * sWo0[f * F + lane] + tf * sWo1[f * F + lane];
    }

    float I = 1.0f / (1.0f + expf(-ai));
    float T = tanhf(ac);
    float C = I * T;
    float O = 1.0f / (1.0f + expf(-(ao + sWc2[lane] * C)));
    float H = O * tanhf(C);
    float r = fmaxf(H, 0.0f) * sLw[lane];

    // warp sum over the 32 output features
#pragma unroll
    for (int off = 16; off > 0; off >>= 1)
        r += __shfl_xor_sync(0xffffffffu, r, off);
    if (lane == 0) out[node] = r + sLb;
}

// ---------------------------------------------------------------------------
extern "C" void kernel_launch(void* const* d_in, const int* in_sizes, int n_in,
                              void* d_out, int out_size) {
    const float* x     = (const float*)d_in[0];
    const void*  ei    = d_in[1];
    const float* ew    = (const float*)d_in[2];
    const float* Wx    = (const float*)d_in[3];
    const float* bx    = (const float*)d_in[4];
    // d_in[5] = Wh (dead: H_prev == 0)
    const float* bh    = (const float*)d_in[6];
    const float* wc    = (const float*)d_in[7];
    const float* bgate = (const float*)d_in[8];
    const float* linw  = (const float*)d_in[9];
    const float* linb  = (const float*)d_in[10];
    float*       out   = (float*)d_out;

    const int N = in_sizes[0] / F;
    const int E = in_sizes[2];

    const int B = 256;
    k_detect<<<1, 1>>>(ei, E, N);
    k_zero<<<(N * F + B - 1) / B, B>>>(N);
    k_degree<<<(E + B - 1) / B, B>>>(ei, ew, E, N);
    k_dinv<<<(N + B - 1) / B, B>>>(N);
    k_norm<<<(E + B - 1) / B, B>>>(ei, ew, E, N);
    k_scatter<<<((long long)E * 8 + B - 1) / B, B>>>(x, ei, E, N);
    // 8 warps (nodes) per block
    k_gates<<<(N + 7) / 8, B>>>(x, Wx, bx, bh, wc, bgate, linw, linb, out, N);
}

// round 5
// speedup vs baseline: 1.0135x; 1.0135x over previous
#include <cuda_runtime.h>
#include <cuda_bf16.h>
#include <math.h>

// Problem constants (fixed by the dataset)
#define MAXN 100000
#define MAXE 1600000
#define F 32            // F_IN == F_OUT == 32

// Scratch (static device globals; no allocation allowed)
__device__ int   d_idx64;            // 1 if edge_index is int64, 0 if int32
__device__ float d_deg[MAXN];        // degree, then overwritten with dinv
__device__ int   d_src[MAXE];        // int32 source indices
__device__ int   d_dst[MAXE];        // int32 dest indices
__device__ float d_w[MAXE];          // weight, zeroed for self loops / bad edges
__device__ float d_tx1[MAXN * F];    // L_hat @ x

// ---------------------------------------------------------------------------
// K-1: detect edge_index dtype (one warp, parallel probes + ballot).
// Under int64 interpretation of int32 data, a value is >= 2^32 whenever the
// odd word is nonzero (prob 1-1e-5 per sample); 64 samples -> certain.
// ---------------------------------------------------------------------------
__global__ void k_detect(const void* __restrict__ ei, int E, int n) {
    const long long* p = (const long long*)ei;
    int lane = threadIdx.x;
    long long a = p[lane];
    long long b = p[E + lane];
    int bad = (a < 0 || a >= n || b < 0 || b >= n) ? 1 : 0;
    unsigned m = __ballot_sync(0xffffffffu, bad);
    if (lane == 0) d_idx64 = (m == 0u) ? 1 : 0;
}

// ---------------------------------------------------------------------------
// K0: zero deg and tx1
// ---------------------------------------------------------------------------
__global__ void k_zero(int n) {
    int i = blockIdx.x * blockDim.x + threadIdx.x;
    int tot = n * F;
    if (i < tot) d_tx1[i] = 0.0f;
    if (i < n)   d_deg[i] = 0.0f;
}

// ---------------------------------------------------------------------------
// K1: single pass over edge_index:
//   - convert indices to int32 scratch (d_src/d_dst)
//   - store self-loop/bounds-zeroed weight (d_w)
//   - accumulate degree: deg[src] += w
// ---------------------------------------------------------------------------
__global__ void k_prep(const void* __restrict__ ei,
                       const float* __restrict__ ew, int E, int n) {
    int e = blockIdx.x * blockDim.x + threadIdx.x;
    if (e >= E) return;
    int s, d;
    if (d_idx64) {
        const long long* p = (const long long*)ei;
        s = (int)p[e];
        d = (int)p[E + e];
    } else {
        const int* p = (const int*)ei;
        s = p[e];
        d = p[E + e];
    }
    float w = ew[e];
    if ((unsigned)s >= (unsigned)n || (unsigned)d >= (unsigned)n) {
        s = 0; d = 0; w = 0.0f;
    }
    if (s == d) w = 0.0f;
    d_src[e] = s;
    d_dst[e] = d;
    d_w[e]   = w;
    if (w != 0.0f) atomicAdd(&d_deg[s], w);
}

// ---------------------------------------------------------------------------
// K2: deg -> dinv = deg>0 ? rsqrt(deg) : 0
// ---------------------------------------------------------------------------
__global__ void k_dinv(int n) {
    int i = blockIdx.x * blockDim.x + threadIdx.x;
    if (i >= n) return;
    float v = d_deg[i];
    d_deg[i] = (v > 0.0f) ? rsqrtf(v) : 0.0f;
}

// ---------------------------------------------------------------------------
// K3: scatter  tx1[dst] += (-dinv[src]*w*dinv[dst]) * x[src]
// Norm computed inline (no separate pass). 8 threads per edge, one float4
// quad each; the 8 lanes of an edge load identical s/d/w/dinv values ->
// single L2 request per warp per distinct address.
// ---------------------------------------------------------------------------
__global__ void k_scatter(const float* __restrict__ x, int E) {
    int t = blockIdx.x * blockDim.x + threadIdx.x;
    int e = t >> 3;
    int q = t & 7;
    if (e >= E) return;
    float w = d_w[e];
    if (w == 0.0f) return;
    int s = d_src[e];
    int d = d_dst[e];
    float c = -d_deg[s] * w * d_deg[d];
    if (c == 0.0f) return;
    const float4* x4 = reinterpret_cast<const float4*>(x);
    float4 xv = x4[s * (F / 4) + q];
    float* dst = &d_tx1[d * F + q * 4];
    asm volatile("red.global.add.v4.f32 [%0], {%1, %2, %3, %4};"
                 :: "l"(dst), "f"(c * xv.x), "f"(c * xv.y),
                    "f"(c * xv.z), "f"(c * xv.w)
                 : "memory");
}

// ---------------------------------------------------------------------------
// K4: gates + output.  Since H_prev = C_prev = 0:
//   I = sigmoid(x@Wx[0,0] + tx1@Wx[0,1] + bx[0] + bh[0] + b_gate[0])
//   T = tanh   (x@Wx[2,0] + tx1@Wx[2,1] + bx[2] + bh[2] + b_gate[2])
//   C = I*T
//   O = sigmoid(x@Wx[3,0] + tx1@Wx[3,1] + bx[3] + bh[3] + b_gate[3] + wc[2]*C)
//   H = O*tanh(C);  out = relu(H)@lin_w + lin_b
// One warp per node, lane = output feature.
// ---------------------------------------------------------------------------
__global__ void k_gates(const float* __restrict__ x,
                        const float* __restrict__ Wx,
                        const float* __restrict__ bx,
                        const float* __restrict__ bh,
                        const float* __restrict__ wc,
                        const float* __restrict__ bgate,
                        const float* __restrict__ linw,
                        const float* __restrict__ linb,
                        float* __restrict__ out, int n) {
    __shared__ float sWi0[F * F], sWi1[F * F];
    __shared__ float sWc0[F * F], sWc1[F * F];
    __shared__ float sWo0[F * F], sWo1[F * F];
    __shared__ float sBi[F], sBc[F], sBo[F], sWc2[F], sLw[F];
    __shared__ float sLb;

    int tid = threadIdx.x;
    // Wx layout: [4][2][32][32]; matrix (g,k) starts at (g*2+k)*F*F
    for (int i = tid; i < F * F; i += blockDim.x) {
        sWi0[i] = Wx[(0 * 2 + 0) * F * F + i];
        sWi1[i] = Wx[(0 * 2 + 1) * F * F + i];
        sWc0[i] = Wx[(2 * 2 + 0) * F * F + i];
        sWc1[i] = Wx[(2 * 2 + 1) * F * F + i];
        sWo0[i] = Wx[(3 * 2 + 0) * F * F + i];
        sWo1[i] = Wx[(3 * 2 + 1) * F * F + i];
    }
    if (tid < F) {
        sBi[tid]  = bx[0 * F + tid] + bh[0 * F + tid] + bgate[0 * F + tid];
        sBc[tid]  = bx[2 * F + tid] + bh[2 * F + tid] + bgate[2 * F + tid];
        sBo[tid]  = bx[3 * F + tid] + bh[3 * F + tid] + bgate[3 * F + tid];
        sWc2[tid] = wc[2 * F + tid];
        sLw[tid]  = linw[tid];
        if (tid == 0) sLb = linb[0];
    }
    __syncthreads();

    int warp = tid >> 5;
    int lane = tid & 31;
    int node = blockIdx.x * (blockDim.x >> 5) + warp;
    if (node >= n) return;

    float xr = x[node * F + lane];
    float tr = d_tx1[node * F + lane];

    float ai = sBi[lane];
    float ac = sBc[lane];
    float ao = sBo[lane];

#pragma unroll
    for (int f = 0; f < F; f++) {
        float xf = __shfl_sync(0xffffffffu, xr, f);
        float tf = __shfl_sync(0xffffffffu, tr, f);
        ai += xf * sWi0[f * F + lane] + tf * sWi1[f * F + lane];
        ac += xf * sWc0[f * F + lane] + tf * sWc1[f * F + lane];
        ao += xf * sWo0[f * F + lane] + tf * sWo1[f * F + lane];
    }

    float I = 1.0f / (1.0f + expf(-ai));
    float T = tanhf(ac);
    float C = I * T;
    float O = 1.0f / (1.0f + expf(-(ao + sWc2[lane] * C)));
    float H = O * tanhf(C);
    float r = fmaxf(H, 0.0f) * sLw[lane];

    // warp sum over the 32 output features
#pragma unroll
    for (int off = 16; off > 0; off >>= 1)
        r += __shfl_xor_sync(0xffffffffu, r, off);
    if (lane == 0) out[node] = r + sLb;
}

// ---------------------------------------------------------------------------
extern "C" void kernel_launch(void* const* d_in, const int* in_sizes, int n_in,
                              void* d_out, int out_size) {
    const float* x     = (const float*)d_in[0];
    const void*  ei    = d_in[1];
    const float* ew    = (const float*)d_in[2];
    const float* Wx    = (const float*)d_in[3];
    const float* bx    = (const float*)d_in[4];
    // d_in[5] = Wh (dead: H_prev == 0)
    const float* bh    = (const float*)d_in[6];
    const float* wc    = (const float*)d_in[7];
    const float* bgate = (const float*)d_in[8];
    const float* linw  = (const float*)d_in[9];
    const float* linb  = (const float*)d_in[10];
    float*       out   = (float*)d_out;

    const int N = in_sizes[0] / F;
    const int E = in_sizes[2];

    const int B = 256;
    k_detect<<<1, 32>>>(ei, E, N);
    k_zero<<<(N * F + B - 1) / B, B>>>(N);
    k_prep<<<(E + B - 1) / B, B>>>(ei, ew, E, N);
    k_dinv<<<(N + B - 1) / B, B>>>(N);
    k_scatter<<<((long long)E * 8 + B - 1) / B, B>>>(x, E);
    // 8 warps (nodes) per block
    k_gates<<<(N + 7) / 8, B>>>(x, Wx, bx, bh, wc, bgate, linw, linb, out, N);
}